// round 15
// baseline (speedup 1.0000x reference)
#include <cuda_runtime.h>
#include <cuda_fp16.h>
#include <cstdint>

// ---------------- problem constants ----------------
#define M_TOK 2048
#define K_DIM 2048
#define N_DIM 1408
#define N_EXP 8
#define TOP_K 2
#define CAP   1024
#define N_ROWS (M_TOK * TOP_K)
#define W_ELEMS (N_EXP * N_DIM * K_DIM)

// ---------------- scratch ----------------
__device__ int    g_cnt[N_EXP];
__device__ int    g_slot[N_ROWS];
__device__ __half g_x16 [(size_t)N_EXP * CAP * K_DIM];
__device__ __half g_act [(size_t)N_EXP * CAP * N_DIM];
__device__ __half g_stage[(size_t)N_EXP * CAP * K_DIM];
__device__ __half g_gw16[W_ELEMS];
__device__ __half g_uw16[W_ELEMS];
__device__ __half g_dw16[W_ELEMS];

// ---------------- helpers (baseline sm_80 ISA) ----------------
__device__ __forceinline__ uint32_t smem_u32(const void* p) {
    uint32_t a;
    asm("{ .reg .u64 t; cvta.to.shared.u64 t, %1; cvt.u32.u64 %0, t; }" : "=r"(a) : "l"(p));
    return a;
}
__device__ __forceinline__ void cp16(uint32_t s, const void* g) {
    asm volatile("cp.async.cg.shared.global [%0], [%1], 16;" :: "r"(s), "l"(g));
}
#define CP_COMMIT() asm volatile("cp.async.commit_group;" ::: "memory")
#define CP_WAIT2()  asm volatile("cp.async.wait_group 2;" ::: "memory")
#define CP_WAIT1()  asm volatile("cp.async.wait_group 1;" ::: "memory")
#define CP_WAIT0()  asm volatile("cp.async.wait_group 0;" ::: "memory")
__device__ __forceinline__ void ldsm4(uint32_t* r, uint32_t addr) {
    asm volatile("ldmatrix.sync.aligned.m8n8.x4.shared.b16 {%0,%1,%2,%3}, [%4];"
                 : "=r"(r[0]), "=r"(r[1]), "=r"(r[2]), "=r"(r[3]) : "r"(addr));
}
__device__ __forceinline__ void mma16816(float* c, const uint32_t* a, uint32_t b0, uint32_t b1) {
    asm volatile("mma.sync.aligned.m16n8k16.row.col.f32.f16.f16.f32 "
        "{%0,%1,%2,%3},{%4,%5,%6,%7},{%8,%9},{%0,%1,%2,%3};"
        : "+f"(c[0]), "+f"(c[1]), "+f"(c[2]), "+f"(c[3])
        : "r"(a[0]), "r"(a[1]), "r"(a[2]), "r"(a[3]), "r"(b0), "r"(b1));
}
__device__ __forceinline__ uint2 pk4(float4 v) {
    __half2 h0 = __floats2half2_rn(v.x, v.y), h1 = __floats2half2_rn(v.z, v.w);
    return make_uint2(*reinterpret_cast<uint32_t*>(&h0), *reinterpret_cast<uint32_t*>(&h1));
}
__device__ __forceinline__ float swiglu(float g, float u) {
    g = fminf(g, 10.0f);
    u = fminf(fmaxf(u, -10.0f), 10.0f);
    return (g / (1.0f + __expf(-g))) * u;
}
__device__ __forceinline__ uint32_t swz(int row, int c) {
    return (uint32_t)(row * 64 + ((c ^ ((row >> 1) & 3)) << 4));
}

// ---------------- prep ----------------
__global__ void zero_cnt() { if (threadIdx.x < N_EXP) g_cnt[threadIdx.x] = 0; }

// planes 0-1: GW/UW fp32->fp16 with 4x per-thread ILP; plane 2: route+gather
#define CONV_BLKX (W_ELEMS / 4 / 256 / 4)      // 5632 blocks per matrix
__global__ void __launch_bounds__(256) prep_kernel(const float* __restrict__ GW,
                                                   const float* __restrict__ UW,
                                                   const int* __restrict__ idx,
                                                   const float* __restrict__ H) {
    if (blockIdx.y < 2) {
        const float* src = (blockIdx.y == 0) ? GW : UW;
        __half* dst = (blockIdx.y == 0) ? g_gw16 : g_uw16;
        const size_t base = (size_t)blockIdx.x * 1024 + threadIdx.x;
        const float4* s4 = (const float4*)src;
        float4 v0 = s4[base];
        float4 v1 = s4[base + 256];
        float4 v2 = s4[base + 512];
        float4 v3 = s4[base + 768];
        uint2* d2 = (uint2*)dst;
        d2[base]       = pk4(v0);
        d2[base + 256] = pk4(v1);
        d2[base + 512] = pk4(v2);
        d2[base + 768] = pk4(v3);
        return;
    }
    const int r = blockIdx.x;
    if (r >= N_ROWS) return;
    __shared__ int ss;
    if (threadIdx.x == 0) {
        int e = idx[r];
        int p = atomicAdd(&g_cnt[e], 1);
        int s = (p < CAP) ? (e * CAP + p) : -1;
        g_slot[r] = s;
        ss = s;
    }
    __syncthreads();
    const int s = ss;
    if (s < 0) return;
    const float4* src = (const float4*)(H + (size_t)(r >> 1) * K_DIM);
    uint2* dst = (uint2*)(g_x16 + (size_t)s * K_DIM);
    float4 v0 = src[threadIdx.x];
    float4 v1 = src[threadIdx.x + 256];
    dst[threadIdx.x]       = pk4(v0);
    dst[threadIdx.x + 256] = pk4(v1);
}

// ---------------- GEMMs (4-stage cp.async pipeline; R6 config) ----------------
#define STAGE_B 16384
#define NSTAGE  4
extern __shared__ char smc[];

__device__ __forceinline__ void pipe_wait(int kt, int NT) {
    int rem = NT - 1 - kt;
    if (rem >= 2)      CP_WAIT2();
    else if (rem == 1) CP_WAIT1();
    else               CP_WAIT0();
}

// GEMM1: G = X@GW^T, U = X@UW^T (CTA 128m x 64n each), SwiGLU -> g_act
// Grid y in [0,22): gemm tiles. y in [22,44): DW fp32->fp16 conversion planes.
// stage: A(128rows)@0  G(64)@8192  U(64)@12288
__global__ void __launch_bounds__(256, 2) gemm1_tc(const float* __restrict__ DW) {
    if (blockIdx.y >= 22) {
        // ---- DW conversion plane: batched MLP-4 loads ----
        const int cid = (blockIdx.y - 22) * 64 + blockIdx.x * 8 + blockIdx.z;
        const size_t base = (size_t)cid * 4096 + threadIdx.x;
        const float4* src = (const float4*)DW;
        uint2* dst = (uint2*)g_dw16;
#pragma unroll
        for (int b = 0; b < 4; b++) {
            float4 v0 = src[base + (size_t)(4 * b + 0) * 256];
            float4 v1 = src[base + (size_t)(4 * b + 1) * 256];
            float4 v2 = src[base + (size_t)(4 * b + 2) * 256];
            float4 v3 = src[base + (size_t)(4 * b + 3) * 256];
            dst[base + (size_t)(4 * b + 0) * 256] = pk4(v0);
            dst[base + (size_t)(4 * b + 1) * 256] = pk4(v1);
            dst[base + (size_t)(4 * b + 2) * 256] = pk4(v2);
            dst[base + (size_t)(4 * b + 3) * 256] = pk4(v3);
        }
        return;
    }

    const int e = blockIdx.z;
    int cnt = g_cnt[e]; if (cnt > CAP) cnt = CAP;
    const int m0 = blockIdx.x * 128;
    if (m0 >= cnt) return;
    const int n0 = blockIdx.y * 64;

    const int tid = threadIdx.x, lane = tid & 31, wid = tid >> 5;
    const int wm = wid >> 2, wn = wid & 3;
    const int gq = lane >> 2, tg = lane & 3;
    const int lane15 = lane & 15, lhi = lane >> 4;

    const uint32_t su = smem_u32(smc);

    const int lrow = tid >> 2, lc = tid & 3;
    const __half* pa0 = g_x16 + ((size_t)(e * CAP + m0) + lrow) * K_DIM + lc * 8;
    const __half* pa1 = pa0 + (size_t)64 * K_DIM;
    const __half* pg  = g_gw16 + ((size_t)e * N_DIM + n0 + lrow) * K_DIM + lc * 8;
    const __half* pu  = g_uw16 + ((size_t)e * N_DIM + n0 + lrow) * K_DIM + lc * 8;
    const uint32_t soA0 = swz(lrow, lc), soA1 = swz(lrow + 64, lc);
    const uint32_t soG = 8192 + swz(lrow, lc), soU = 12288 + swz(lrow, lc);

    auto load = [&](int kt) {
        const uint32_t sb = su + (uint32_t)(kt % NSTAGE) * STAGE_B;
        const int ko = kt * 32;
        cp16(sb + soA0, pa0 + ko);
        cp16(sb + soA1, pa1 + ko);
        cp16(sb + soG,  pg  + ko);
        cp16(sb + soU,  pu  + ko);
        CP_COMMIT();
    };

    int aoff[4], axr[4];
#pragma unroll
    for (int i = 0; i < 4; i++) {
        int r = wm * 64 + i * 16 + lane15;
        aoff[i] = r * 64; axr[i] = (r >> 1) & 3;
    }
    const int brw = wn * 16 + lane15;
    const int boff = brw * 64, bxr = (brw >> 1) & 3;

    float cG[4][2][4] = {}, cU[4][2][4] = {};

    const int NT = K_DIM / 32;   // 64
    load(0); load(1); load(2);
    for (int kt = 0; kt < NT; ++kt) {
        pipe_wait(kt, NT);
        __syncthreads();
        if (kt + 3 < NT) load(kt + 3);

        const uint32_t sb = su + (uint32_t)(kt % NSTAGE) * STAGE_B;
#pragma unroll
        for (int kh = 0; kh < 2; ++kh) {
            const int ch = 2 * kh + lhi;
            uint32_t bg[4], bu[4];
            ldsm4(bg, sb + 8192  + boff + ((ch ^ bxr) << 4));
            ldsm4(bu, sb + 12288 + boff + ((ch ^ bxr) << 4));
#pragma unroll
            for (int i = 0; i < 4; i++) {
                uint32_t a[4];
                ldsm4(a, sb + aoff[i] + ((ch ^ axr[i]) << 4));
                mma16816(cG[i][0], a, bg[0], bg[2]);
                mma16816(cG[i][1], a, bg[1], bg[3]);
                mma16816(cU[i][0], a, bu[0], bu[2]);
                mma16816(cU[i][1], a, bu[1], bu[3]);
            }
        }
    }

#pragma unroll
    for (int i = 0; i < 4; i++) {
        int r0 = wm * 64 + i * 16 + gq;
        int mg0 = m0 + r0, mg1 = mg0 + 8;
        __half* row0 = g_act + ((size_t)e * CAP + mg0) * N_DIM + n0;
        __half* row1 = g_act + ((size_t)e * CAP + mg1) * N_DIM + n0;
#pragma unroll
        for (int j = 0; j < 2; j++) {
            int col = wn * 16 + j * 8 + tg * 2;
            if (mg0 < cnt)
                *(__half2*)(row0 + col) = __floats2half2_rn(
                    swiglu(cG[i][j][0], cU[i][j][0]), swiglu(cG[i][j][1], cU[i][j][1]));
            if (mg1 < cnt)
                *(__half2*)(row1 + col) = __floats2half2_rn(
                    swiglu(cG[i][j][2], cU[i][j][2]), swiglu(cG[i][j][3], cU[i][j][3]));
        }
    }
}

// GEMM2: D = act@DW^T (CTA 128m x 128n) -> g_stage (fp16, plain stores)
// stage: A(128rows)@0  B(128rows)@8192
__global__ void __launch_bounds__(256, 2) gemm2_tc() {
    const int e = blockIdx.z;
    int cnt = g_cnt[e]; if (cnt > CAP) cnt = CAP;
    const int m0 = blockIdx.x * 128;
    if (m0 >= cnt) return;
    const int n0 = blockIdx.y * 128;

    const int tid = threadIdx.x, lane = tid & 31, wid = tid >> 5;
    const int wm = wid >> 2, wn = wid & 3;
    const int gq = lane >> 2, tg = lane & 3;
    const int lane15 = lane & 15, lhi = lane >> 4;

    const uint32_t su = smem_u32(smc);

    const int lrow = tid >> 2, lc = tid & 3;
    const __half* pa0 = g_act + ((size_t)(e * CAP + m0) + lrow) * N_DIM + lc * 8;
    const __half* pa1 = pa0 + (size_t)64 * N_DIM;
    const __half* pb0 = g_dw16 + ((size_t)e * K_DIM + n0 + lrow) * N_DIM + lc * 8;
    const __half* pb1 = pb0 + (size_t)64 * N_DIM;
    const uint32_t soA0 = swz(lrow, lc), soA1 = swz(lrow + 64, lc);
    const uint32_t soB0 = 8192 + soA0, soB1 = 8192 + soA1;

    auto load = [&](int kt) {
        const uint32_t sb = su + (uint32_t)(kt % NSTAGE) * STAGE_B;
        const int ko = kt * 32;
        cp16(sb + soA0, pa0 + ko);
        cp16(sb + soA1, pa1 + ko);
        cp16(sb + soB0, pb0 + ko);
        cp16(sb + soB1, pb1 + ko);
        CP_COMMIT();
    };

    int aoff[4], axr[4];
#pragma unroll
    for (int i = 0; i < 4; i++) {
        int r = wm * 64 + i * 16 + lane15;
        aoff[i] = r * 64; axr[i] = (r >> 1) & 3;
    }
    int boff[2], bxr[2];
#pragma unroll
    for (int j = 0; j < 2; j++) {
        int r = wn * 32 + j * 16 + lane15;
        boff[j] = 8192 + r * 64; bxr[j] = (r >> 1) & 3;
    }

    float c[4][4][4] = {};

    const int NT = N_DIM / 32;   // 44
    load(0); load(1); load(2);
    for (int kt = 0; kt < NT; ++kt) {
        pipe_wait(kt, NT);
        __syncthreads();
        if (kt + 3 < NT) load(kt + 3);

        const uint32_t sb = su + (uint32_t)(kt % NSTAGE) * STAGE_B;
#pragma unroll
        for (int kh = 0; kh < 2; ++kh) {
            const int ch = 2 * kh + lhi;
            uint32_t b0[4], b1[4];
            ldsm4(b0, sb + boff[0] + ((ch ^ bxr[0]) << 4));
            ldsm4(b1, sb + boff[1] + ((ch ^ bxr[1]) << 4));
#pragma unroll
            for (int i = 0; i < 4; i++) {
                uint32_t a[4];
                ldsm4(a, sb + aoff[i] + ((ch ^ axr[i]) << 4));
                mma16816(c[i][0], a, b0[0], b0[2]);
                mma16816(c[i][1], a, b0[1], b0[3]);
                mma16816(c[i][2], a, b1[0], b1[2]);
                mma16816(c[i][3], a, b1[1], b1[3]);
            }
        }
    }

#pragma unroll
    for (int i = 0; i < 4; i++) {
        int r0 = wm * 64 + i * 16 + gq, r1 = r0 + 8;
        bool v0 = (m0 + r0) < cnt, v1 = (m0 + r1) < cnt;
        __half* o0 = g_stage + ((size_t)e * CAP + m0 + r0) * K_DIM + n0;
        __half* o1 = g_stage + ((size_t)e * CAP + m0 + r1) * K_DIM + n0;
#pragma unroll
        for (int j = 0; j < 4; j++) {
            int col = wn * 32 + j * 8 + tg * 2;
            if (v0) *(__half2*)(o0 + col) = __floats2half2_rn(c[i][j][0], c[i][j][1]);
            if (v1) *(__half2*)(o1 + col) = __floats2half2_rn(c[i][j][2], c[i][j][3]);
        }
    }
}

// combine: 32 outputs/thread, all 8 slot-loads in flight before any math
__global__ void __launch_bounds__(256) combine_kernel(const float* __restrict__ gate,
                                                      float* __restrict__ out) {
    int gid = blockIdx.x * 256 + threadIdx.x;    // over M*K/32
    int t = gid >> 6;                            // K/32 = 64 chunks per token
    int c = (gid & 63) * 32;
    int s0 = g_slot[2 * t], s1 = g_slot[2 * t + 1];
    float g0 = gate[2 * t], g1 = gate[2 * t + 1];

    uint4 a[4], b[4];
    const bool h0ok = (s0 >= 0), h1ok = (s1 >= 0);
    const uint4* p0 = (const uint4*)(g_stage + (size_t)(h0ok ? s0 : 0) * K_DIM + c);
    const uint4* p1 = (const uint4*)(g_stage + (size_t)(h1ok ? s1 : 0) * K_DIM + c);
#pragma unroll
    for (int q = 0; q < 4; q++) a[q] = p0[q];
#pragma unroll
    for (int q = 0; q < 4; q++) b[q] = p1[q];
    if (!h0ok) g0 = 0.0f;
    if (!h1ok) g1 = 0.0f;

    float4* po = (float4*)(out + (size_t)t * K_DIM + c);
#pragma unroll
    for (int q = 0; q < 4; q++) {
        const __half2* ha = (const __half2*)&a[q];
        const __half2* hb = (const __half2*)&b[q];
#pragma unroll
        for (int hq = 0; hq < 2; hq++) {
            float2 fa0 = __half22float2(ha[2 * hq]);
            float2 fa1 = __half22float2(ha[2 * hq + 1]);
            float2 fb0 = __half22float2(hb[2 * hq]);
            float2 fb1 = __half22float2(hb[2 * hq + 1]);
            po[q * 2 + hq] = make_float4(g0 * fa0.x + g1 * fb0.x,
                                         g0 * fa0.y + g1 * fb0.y,
                                         g0 * fa1.x + g1 * fb1.x,
                                         g0 * fa1.y + g1 * fb1.y);
        }
    }
}

// ---------------------------------------------------------------------------
extern "C" void kernel_launch(void* const* d_in, const int* in_sizes, int n_in,
                              void* d_out, int out_size) {
    const float* H   = (const float*)d_in[0];
    const int*   IDX = (const int*)  d_in[1];
    const float* G   = (const float*)d_in[2];
    const float* GW  = (const float*)d_in[3];
    const float* UW  = (const float*)d_in[4];
    const float* DW  = (const float*)d_in[5];
    float* OUT = (float*)d_out;

    const int gsm = NSTAGE * STAGE_B;   // 64KB
    cudaFuncSetAttribute(gemm1_tc, cudaFuncAttributeMaxDynamicSharedMemorySize, gsm);
    cudaFuncSetAttribute(gemm2_tc, cudaFuncAttributeMaxDynamicSharedMemorySize, gsm);

    zero_cnt<<<1, 32>>>();
    dim3 pg(CONV_BLKX, 3);              // planes 0-1: GW/UW (ILP4); 2: dispatch
    prep_kernel<<<pg, 256>>>(GW, UW, IDX, H);

    dim3 g1(CAP / 128, 44, N_EXP);      // y<22: gemm tiles; y>=22: DW conversion
    gemm1_tc<<<g1, 256, gsm>>>(DW);
    dim3 g2(CAP / 128, K_DIM / 128, N_EXP);        // 8 x 16 x 8
    gemm2_tc<<<g2, 256, gsm>>>();

    combine_kernel<<<M_TOK * K_DIM / 32 / 256, 256>>>(G, OUT);
}

// round 16
// speedup vs baseline: 1.0076x; 1.0076x over previous
#include <cuda_runtime.h>
#include <cuda_fp16.h>
#include <cstdint>

// ---------------- problem constants ----------------
#define M_TOK 2048
#define K_DIM 2048
#define N_DIM 1408
#define N_EXP 8
#define TOP_K 2
#define CAP   1024
#define N_ROWS (M_TOK * TOP_K)
#define W_ELEMS (N_EXP * N_DIM * K_DIM)

// ---------------- scratch ----------------
__device__ int    g_cnt[N_EXP];
__device__ int    g_slot[N_ROWS];
__device__ __half g_x16 [(size_t)N_EXP * CAP * K_DIM];
__device__ __half g_act [(size_t)N_EXP * CAP * N_DIM];
__device__ __half g_stage[(size_t)N_EXP * CAP * K_DIM];
__device__ __half g_gw16[W_ELEMS];
__device__ __half g_uw16[W_ELEMS];
__device__ __half g_dw16[W_ELEMS];

// ---------------- helpers (baseline sm_80 ISA) ----------------
__device__ __forceinline__ uint32_t smem_u32(const void* p) {
    uint32_t a;
    asm("{ .reg .u64 t; cvta.to.shared.u64 t, %1; cvt.u32.u64 %0, t; }" : "=r"(a) : "l"(p));
    return a;
}
__device__ __forceinline__ void cp16(uint32_t s, const void* g) {
    asm volatile("cp.async.cg.shared.global [%0], [%1], 16;" :: "r"(s), "l"(g));
}
#define CP_COMMIT() asm volatile("cp.async.commit_group;" ::: "memory")
#define CP_WAIT2()  asm volatile("cp.async.wait_group 2;" ::: "memory")
#define CP_WAIT1()  asm volatile("cp.async.wait_group 1;" ::: "memory")
#define CP_WAIT0()  asm volatile("cp.async.wait_group 0;" ::: "memory")
__device__ __forceinline__ void ldsm4(uint32_t* r, uint32_t addr) {
    asm volatile("ldmatrix.sync.aligned.m8n8.x4.shared.b16 {%0,%1,%2,%3}, [%4];"
                 : "=r"(r[0]), "=r"(r[1]), "=r"(r[2]), "=r"(r[3]) : "r"(addr));
}
__device__ __forceinline__ void mma16816(float* c, const uint32_t* a, uint32_t b0, uint32_t b1) {
    asm volatile("mma.sync.aligned.m16n8k16.row.col.f32.f16.f16.f32 "
        "{%0,%1,%2,%3},{%4,%5,%6,%7},{%8,%9},{%0,%1,%2,%3};"
        : "+f"(c[0]), "+f"(c[1]), "+f"(c[2]), "+f"(c[3])
        : "r"(a[0]), "r"(a[1]), "r"(a[2]), "r"(a[3]), "r"(b0), "r"(b1));
}
__device__ __forceinline__ uint2 pk4(float4 v) {
    __half2 h0 = __floats2half2_rn(v.x, v.y), h1 = __floats2half2_rn(v.z, v.w);
    return make_uint2(*reinterpret_cast<uint32_t*>(&h0), *reinterpret_cast<uint32_t*>(&h1));
}
__device__ __forceinline__ float swiglu(float g, float u) {
    g = fminf(g, 10.0f);
    u = fminf(fmaxf(u, -10.0f), 10.0f);
    return (g / (1.0f + __expf(-g))) * u;
}
__device__ __forceinline__ uint32_t swz(int row, int c) {
    return (uint32_t)(row * 64 + ((c ^ ((row >> 1) & 3)) << 4));
}

// ---------------- prep ----------------
// planes 0-1: GW/UW fp32->fp16 with 4x per-thread ILP; plane 2: route+gather
#define CONV_BLKX (W_ELEMS / 4 / 256 / 4)      // 5632 blocks per matrix
__global__ void __launch_bounds__(256) prep_kernel(const float* __restrict__ GW,
                                                   const float* __restrict__ UW,
                                                   const int* __restrict__ idx,
                                                   const float* __restrict__ H) {
    if (blockIdx.y < 2) {
        const float* src = (blockIdx.y == 0) ? GW : UW;
        __half* dst = (blockIdx.y == 0) ? g_gw16 : g_uw16;
        const size_t base = (size_t)blockIdx.x * 1024 + threadIdx.x;
        const float4* s4 = (const float4*)src;
        float4 v0 = s4[base];
        float4 v1 = s4[base + 256];
        float4 v2 = s4[base + 512];
        float4 v3 = s4[base + 768];
        uint2* d2 = (uint2*)dst;
        d2[base]       = pk4(v0);
        d2[base + 256] = pk4(v1);
        d2[base + 512] = pk4(v2);
        d2[base + 768] = pk4(v3);
        return;
    }
    const int r = blockIdx.x;
    if (r >= N_ROWS) return;
    __shared__ int ss;
    if (threadIdx.x == 0) {
        int e = idx[r];
        int p = atomicAdd(&g_cnt[e], 1);
        int s = (p < CAP) ? (e * CAP + p) : -1;
        g_slot[r] = s;
        ss = s;
    }
    __syncthreads();
    const int s = ss;
    if (s < 0) return;
    const float4* src = (const float4*)(H + (size_t)(r >> 1) * K_DIM);
    uint2* dst = (uint2*)(g_x16 + (size_t)s * K_DIM);
    float4 v0 = src[threadIdx.x];
    float4 v1 = src[threadIdx.x + 256];
    dst[threadIdx.x]       = pk4(v0);
    dst[threadIdx.x + 256] = pk4(v1);
}

// ---------------- GEMMs (4-stage cp.async pipeline; R6 config) ----------------
#define STAGE_B 16384
#define NSTAGE  4
extern __shared__ char smc[];

__device__ __forceinline__ void pipe_wait(int kt, int NT) {
    int rem = NT - 1 - kt;
    if (rem >= 2)      CP_WAIT2();
    else if (rem == 1) CP_WAIT1();
    else               CP_WAIT0();
}

// GEMM1: G = X@GW^T, U = X@UW^T (CTA 128m x 64n each), SwiGLU -> g_act
// Grid y in [0,22): gemm tiles. y in [22,44): DW fp32->fp16 conversion planes.
// stage: A(128rows)@0  G(64)@8192  U(64)@12288
__global__ void __launch_bounds__(256, 2) gemm1_tc(const float* __restrict__ DW) {
    if (blockIdx.y >= 22) {
        const int cid = (blockIdx.y - 22) * 64 + blockIdx.x * 8 + blockIdx.z;
        const size_t base = (size_t)cid * 4096 + threadIdx.x;
        const float4* src = (const float4*)DW;
        uint2* dst = (uint2*)g_dw16;
#pragma unroll
        for (int b = 0; b < 4; b++) {
            float4 v0 = src[base + (size_t)(4 * b + 0) * 256];
            float4 v1 = src[base + (size_t)(4 * b + 1) * 256];
            float4 v2 = src[base + (size_t)(4 * b + 2) * 256];
            float4 v3 = src[base + (size_t)(4 * b + 3) * 256];
            dst[base + (size_t)(4 * b + 0) * 256] = pk4(v0);
            dst[base + (size_t)(4 * b + 1) * 256] = pk4(v1);
            dst[base + (size_t)(4 * b + 2) * 256] = pk4(v2);
            dst[base + (size_t)(4 * b + 3) * 256] = pk4(v3);
        }
        return;
    }

    const int e = blockIdx.z;
    int cnt = g_cnt[e]; if (cnt > CAP) cnt = CAP;
    const int m0 = blockIdx.x * 128;
    if (m0 >= cnt) return;
    const int n0 = blockIdx.y * 64;

    const int tid = threadIdx.x, lane = tid & 31, wid = tid >> 5;
    const int wm = wid >> 2, wn = wid & 3;
    const int gq = lane >> 2, tg = lane & 3;
    const int lane15 = lane & 15, lhi = lane >> 4;

    const uint32_t su = smem_u32(smc);

    const int lrow = tid >> 2, lc = tid & 3;
    const __half* pa0 = g_x16 + ((size_t)(e * CAP + m0) + lrow) * K_DIM + lc * 8;
    const __half* pa1 = pa0 + (size_t)64 * K_DIM;
    const __half* pg  = g_gw16 + ((size_t)e * N_DIM + n0 + lrow) * K_DIM + lc * 8;
    const __half* pu  = g_uw16 + ((size_t)e * N_DIM + n0 + lrow) * K_DIM + lc * 8;
    const uint32_t soA0 = swz(lrow, lc), soA1 = swz(lrow + 64, lc);
    const uint32_t soG = 8192 + swz(lrow, lc), soU = 12288 + swz(lrow, lc);

    auto load = [&](int kt) {
        const uint32_t sb = su + (uint32_t)(kt % NSTAGE) * STAGE_B;
        const int ko = kt * 32;
        cp16(sb + soA0, pa0 + ko);
        cp16(sb + soA1, pa1 + ko);
        cp16(sb + soG,  pg  + ko);
        cp16(sb + soU,  pu  + ko);
        CP_COMMIT();
    };

    int aoff[4], axr[4];
#pragma unroll
    for (int i = 0; i < 4; i++) {
        int r = wm * 64 + i * 16 + lane15;
        aoff[i] = r * 64; axr[i] = (r >> 1) & 3;
    }
    const int brw = wn * 16 + lane15;
    const int boff = brw * 64, bxr = (brw >> 1) & 3;

    float cG[4][2][4] = {}, cU[4][2][4] = {};

    const int NT = K_DIM / 32;   // 64
    load(0); load(1); load(2);
    for (int kt = 0; kt < NT; ++kt) {
        pipe_wait(kt, NT);
        __syncthreads();
        if (kt + 3 < NT) load(kt + 3);

        const uint32_t sb = su + (uint32_t)(kt % NSTAGE) * STAGE_B;
#pragma unroll
        for (int kh = 0; kh < 2; ++kh) {
            const int ch = 2 * kh + lhi;
            // front-issue all 6 LDSMs of this half-step
            uint32_t bg[4], bu[4], a[4][4];
            ldsm4(bg, sb + 8192  + boff + ((ch ^ bxr) << 4));
            ldsm4(bu, sb + 12288 + boff + ((ch ^ bxr) << 4));
#pragma unroll
            for (int i = 0; i < 4; i++)
                ldsm4(a[i], sb + aoff[i] + ((ch ^ axr[i]) << 4));
#pragma unroll
            for (int i = 0; i < 4; i++) {
                mma16816(cG[i][0], a[i], bg[0], bg[2]);
                mma16816(cG[i][1], a[i], bg[1], bg[3]);
                mma16816(cU[i][0], a[i], bu[0], bu[2]);
                mma16816(cU[i][1], a[i], bu[1], bu[3]);
            }
        }
    }

#pragma unroll
    for (int i = 0; i < 4; i++) {
        int r0 = wm * 64 + i * 16 + gq;
        int mg0 = m0 + r0, mg1 = mg0 + 8;
        __half* row0 = g_act + ((size_t)e * CAP + mg0) * N_DIM + n0;
        __half* row1 = g_act + ((size_t)e * CAP + mg1) * N_DIM + n0;
#pragma unroll
        for (int j = 0; j < 2; j++) {
            int col = wn * 16 + j * 8 + tg * 2;
            if (mg0 < cnt)
                *(__half2*)(row0 + col) = __floats2half2_rn(
                    swiglu(cG[i][j][0], cU[i][j][0]), swiglu(cG[i][j][1], cU[i][j][1]));
            if (mg1 < cnt)
                *(__half2*)(row1 + col) = __floats2half2_rn(
                    swiglu(cG[i][j][2], cU[i][j][2]), swiglu(cG[i][j][3], cU[i][j][3]));
        }
    }
}

// GEMM2: D = act@DW^T (CTA 128m x 128n) -> g_stage (fp16, plain stores)
// stage: A(128rows)@0  B(128rows)@8192
__global__ void __launch_bounds__(256, 2) gemm2_tc() {
    const int e = blockIdx.z;
    int cnt = g_cnt[e]; if (cnt > CAP) cnt = CAP;
    const int m0 = blockIdx.x * 128;
    if (m0 >= cnt) return;
    const int n0 = blockIdx.y * 128;

    const int tid = threadIdx.x, lane = tid & 31, wid = tid >> 5;
    const int wm = wid >> 2, wn = wid & 3;
    const int gq = lane >> 2, tg = lane & 3;
    const int lane15 = lane & 15, lhi = lane >> 4;

    const uint32_t su = smem_u32(smc);

    const int lrow = tid >> 2, lc = tid & 3;
    const __half* pa0 = g_act + ((size_t)(e * CAP + m0) + lrow) * N_DIM + lc * 8;
    const __half* pa1 = pa0 + (size_t)64 * N_DIM;
    const __half* pb0 = g_dw16 + ((size_t)e * K_DIM + n0 + lrow) * N_DIM + lc * 8;
    const __half* pb1 = pb0 + (size_t)64 * N_DIM;
    const uint32_t soA0 = swz(lrow, lc), soA1 = swz(lrow + 64, lc);
    const uint32_t soB0 = 8192 + soA0, soB1 = 8192 + soA1;

    auto load = [&](int kt) {
        const uint32_t sb = su + (uint32_t)(kt % NSTAGE) * STAGE_B;
        const int ko = kt * 32;
        cp16(sb + soA0, pa0 + ko);
        cp16(sb + soA1, pa1 + ko);
        cp16(sb + soB0, pb0 + ko);
        cp16(sb + soB1, pb1 + ko);
        CP_COMMIT();
    };

    int aoff[4], axr[4];
#pragma unroll
    for (int i = 0; i < 4; i++) {
        int r = wm * 64 + i * 16 + lane15;
        aoff[i] = r * 64; axr[i] = (r >> 1) & 3;
    }
    int boff[2], bxr[2];
#pragma unroll
    for (int j = 0; j < 2; j++) {
        int r = wn * 32 + j * 16 + lane15;
        boff[j] = 8192 + r * 64; bxr[j] = (r >> 1) & 3;
    }

    float c[4][4][4] = {};

    const int NT = N_DIM / 32;   // 44
    load(0); load(1); load(2);
    for (int kt = 0; kt < NT; ++kt) {
        pipe_wait(kt, NT);
        __syncthreads();
        if (kt + 3 < NT) load(kt + 3);

        const uint32_t sb = su + (uint32_t)(kt % NSTAGE) * STAGE_B;
#pragma unroll
        for (int kh = 0; kh < 2; ++kh) {
            const int ch = 2 * kh + lhi;
            // front-issue all 6 LDSMs of this half-step
            uint32_t b0[4], b1[4], a[4][4];
            ldsm4(b0, sb + boff[0] + ((ch ^ bxr[0]) << 4));
            ldsm4(b1, sb + boff[1] + ((ch ^ bxr[1]) << 4));
#pragma unroll
            for (int i = 0; i < 4; i++)
                ldsm4(a[i], sb + aoff[i] + ((ch ^ axr[i]) << 4));
#pragma unroll
            for (int i = 0; i < 4; i++) {
                mma16816(c[i][0], a[i], b0[0], b0[2]);
                mma16816(c[i][1], a[i], b0[1], b0[3]);
                mma16816(c[i][2], a[i], b1[0], b1[2]);
                mma16816(c[i][3], a[i], b1[1], b1[3]);
            }
        }
    }

#pragma unroll
    for (int i = 0; i < 4; i++) {
        int r0 = wm * 64 + i * 16 + gq, r1 = r0 + 8;
        bool v0 = (m0 + r0) < cnt, v1 = (m0 + r1) < cnt;
        __half* o0 = g_stage + ((size_t)e * CAP + m0 + r0) * K_DIM + n0;
        __half* o1 = g_stage + ((size_t)e * CAP + m0 + r1) * K_DIM + n0;
#pragma unroll
        for (int j = 0; j < 4; j++) {
            int col = wn * 32 + j * 8 + tg * 2;
            if (v0) *(__half2*)(o0 + col) = __floats2half2_rn(c[i][j][0], c[i][j][1]);
            if (v1) *(__half2*)(o1 + col) = __floats2half2_rn(c[i][j][2], c[i][j][3]);
        }
    }
}

// combine: 32 outputs/thread, all 8 slot-loads in flight before any math
__global__ void __launch_bounds__(256) combine_kernel(const float* __restrict__ gate,
                                                      float* __restrict__ out) {
    int gid = blockIdx.x * 256 + threadIdx.x;    // over M*K/32
    int t = gid >> 6;                            // K/32 = 64 chunks per token
    int c = (gid & 63) * 32;
    int s0 = g_slot[2 * t], s1 = g_slot[2 * t + 1];
    float g0 = gate[2 * t], g1 = gate[2 * t + 1];

    uint4 a[4], b[4];
    const bool h0ok = (s0 >= 0), h1ok = (s1 >= 0);
    const uint4* p0 = (const uint4*)(g_stage + (size_t)(h0ok ? s0 : 0) * K_DIM + c);
    const uint4* p1 = (const uint4*)(g_stage + (size_t)(h1ok ? s1 : 0) * K_DIM + c);
#pragma unroll
    for (int q = 0; q < 4; q++) a[q] = p0[q];
#pragma unroll
    for (int q = 0; q < 4; q++) b[q] = p1[q];
    if (!h0ok) g0 = 0.0f;
    if (!h1ok) g1 = 0.0f;

    float4* po = (float4*)(out + (size_t)t * K_DIM + c);
#pragma unroll
    for (int q = 0; q < 4; q++) {
        const __half2* ha = (const __half2*)&a[q];
        const __half2* hb = (const __half2*)&b[q];
#pragma unroll
        for (int hq = 0; hq < 2; hq++) {
            float2 fa0 = __half22float2(ha[2 * hq]);
            float2 fa1 = __half22float2(ha[2 * hq + 1]);
            float2 fb0 = __half22float2(hb[2 * hq]);
            float2 fb1 = __half22float2(hb[2 * hq + 1]);
            po[q * 2 + hq] = make_float4(g0 * fa0.x + g1 * fb0.x,
                                         g0 * fa0.y + g1 * fb0.y,
                                         g0 * fa1.x + g1 * fb1.x,
                                         g0 * fa1.y + g1 * fb1.y);
        }
    }
}

// ---------------------------------------------------------------------------
extern "C" void kernel_launch(void* const* d_in, const int* in_sizes, int n_in,
                              void* d_out, int out_size) {
    const float* H   = (const float*)d_in[0];
    const int*   IDX = (const int*)  d_in[1];
    const float* G   = (const float*)d_in[2];
    const float* GW  = (const float*)d_in[3];
    const float* UW  = (const float*)d_in[4];
    const float* DW  = (const float*)d_in[5];
    float* OUT = (float*)d_out;

    const int gsm = NSTAGE * STAGE_B;   // 64KB
    cudaFuncSetAttribute(gemm1_tc, cudaFuncAttributeMaxDynamicSharedMemorySize, gsm);
    cudaFuncSetAttribute(gemm2_tc, cudaFuncAttributeMaxDynamicSharedMemorySize, gsm);

    // zero expert counters without a kernel launch
    void* cnt_addr = nullptr;
    cudaGetSymbolAddress(&cnt_addr, g_cnt);
    cudaMemsetAsync(cnt_addr, 0, N_EXP * sizeof(int));

    dim3 pg(CONV_BLKX, 3);              // planes 0-1: GW/UW (ILP4); 2: dispatch
    prep_kernel<<<pg, 256>>>(GW, UW, IDX, H);

    dim3 g1(CAP / 128, 44, N_EXP);      // y<22: gemm tiles; y>=22: DW conversion
    gemm1_tc<<<g1, 256, gsm>>>(DW);
    dim3 g2(CAP / 128, K_DIM / 128, N_EXP);        // 8 x 16 x 8
    gemm2_tc<<<g2, 256, gsm>>>();

    combine_kernel<<<M_TOK * K_DIM / 32 / 256, 256>>>(G, OUT);
}